// round 8
// baseline (speedup 1.0000x reference)
#include <cuda_runtime.h>
#include <cuda_bf16.h>
#include <cstdint>

typedef unsigned long long ull;

#define E_DIM 128
#define NPG   32
#define TPB   256
#define PAD   132           // fp32 row stride (floats)
#define XSB   272           // bf16 A-tile row stride (bytes)
#define XH64  17408         // bytes per 64-row bf16 tile (64*272)
#define WHALF 34816         // bytes per 128-row bf16 tile (128*272)
#define WB    69632         // bytes per weight (hi+lo)

// smem byte offsets (same footprint as R6)
#define OFF_W    0          // 69632: current weight hi/lo (full K resident)
#define OFF_X    69632      // 34816: X hi/lo tiles; later V_s fp32 (33792)
#define OFF_C    104448     // 34816: Q_s fp32 (33792); later attn-out hi/lo tiles
#define OFF_D    139264     // 33792: K_s fp32
#define OFF_BIAS 173056     // 512 floats
#define SMEM_TOTAL 175104

__device__ __align__(1024) unsigned char g_wconv[4 * WB];

// ---------- helpers ----------
__device__ __forceinline__ uint32_t s2u(const void* p) {
    uint32_t a;
    asm("{ .reg .u64 t; cvta.to.shared.u64 t, %1; cvt.u32.u64 %0, t; }" : "=r"(a) : "l"(p));
    return a;
}
__device__ __forceinline__ ull pack2(float lo, float hi) {
    ull r; asm("mov.b64 %0, {%1, %2};" : "=l"(r) : "f"(lo), "f"(hi)); return r;
}
__device__ __forceinline__ void unpack2(ull p, float& lo, float& hi) {
    asm("mov.b64 {%0, %1}, %2;" : "=f"(lo), "=f"(hi) : "l"(p));
}
__device__ __forceinline__ void ffma2(ull& d, ull a, ull b) {
    asm("fma.rn.f32x2 %0, %1, %2, %0;" : "+l"(d) : "l"(a), "l"(b));
}
__device__ __forceinline__ ull pack4bf(__nv_bfloat16 a, __nv_bfloat16 b,
                                       __nv_bfloat16 c, __nv_bfloat16 d) {
    uint32_t lo = ((uint32_t)__bfloat16_as_ushort(b) << 16) | __bfloat16_as_ushort(a);
    uint32_t hi = ((uint32_t)__bfloat16_as_ushort(d) << 16) | __bfloat16_as_ushort(c);
    return ((ull)hi << 32) | lo;
}
__device__ __forceinline__ void split4(float4 x, ull& hiw, ull& low) {
    __nv_bfloat16 h0 = __float2bfloat16(x.x), h1 = __float2bfloat16(x.y),
                  h2 = __float2bfloat16(x.z), h3 = __float2bfloat16(x.w);
    __nv_bfloat16 l0 = __float2bfloat16(x.x - __bfloat162float(h0));
    __nv_bfloat16 l1 = __float2bfloat16(x.y - __bfloat162float(h1));
    __nv_bfloat16 l2 = __float2bfloat16(x.z - __bfloat162float(h2));
    __nv_bfloat16 l3 = __float2bfloat16(x.w - __bfloat162float(h3));
    hiw = pack4bf(h0, h1, h2, h3);
    low = pack4bf(l0, l1, l2, l3);
}
__device__ __forceinline__ void ldsm4(uint32_t& r0, uint32_t& r1, uint32_t& r2,
                                      uint32_t& r3, uint32_t a) {
    asm volatile("ldmatrix.sync.aligned.m8n8.x4.shared.b16 {%0,%1,%2,%3}, [%4];"
                 : "=r"(r0), "=r"(r1), "=r"(r2), "=r"(r3) : "r"(a));
}
__device__ __forceinline__ void mma_bf16(float* c, const uint32_t* a,
                                         uint32_t b0, uint32_t b1) {
    asm volatile(
        "mma.sync.aligned.m16n8k16.row.col.f32.bf16.bf16.f32 "
        "{%0,%1,%2,%3}, {%4,%5,%6,%7}, {%8,%9}, {%0,%1,%2,%3};"
        : "+f"(c[0]), "+f"(c[1]), "+f"(c[2]), "+f"(c[3])
        : "r"(a[0]), "r"(a[1]), "r"(a[2]), "r"(a[3]), "r"(b0), "r"(b1));
}
__device__ __forceinline__ void cp16(uint32_t smem, const void* g) {
    asm volatile("cp.async.ca.shared.global [%0], [%1], 16;" :: "r"(smem), "l"(g) : "memory");
}
#define CP_COMMIT() asm volatile("cp.async.commit_group;" ::: "memory")
#define CP_WAIT0()  asm volatile("cp.async.wait_group 0;" ::: "memory")

// ---------- building blocks ----------
// X (64x128 f32, gmem) -> hi/lo bf16 tiles at OFF_X (256 threads)
__device__ __forceinline__ void convert_X(const float* __restrict__ gx, char* raw, int tid) {
    const int row  = tid >> 2;           // 0..63
    const int colb = (tid & 3) * 32;
#pragma unroll
    for (int i = 0; i < 8; i++) {
        const int col = colb + i * 4;
        float4 x = *reinterpret_cast<const float4*>(gx + row * E_DIM + col);
        ull hw, lw; split4(x, hw, lw);
        *(ull*)(raw + OFF_X + row * XSB + col * 2)        = hw;
        *(ull*)(raw + OFF_X + XH64 + row * XSB + col * 2) = lw;
    }
}
// async full weight copy: 4352 x 16B = 69632B (256 threads x 17)
__device__ __forceinline__ void copy_W_async(int wsel, uint32_t sb, int tid) {
    const char* s = reinterpret_cast<const char*>(g_wconv) + wsel * WB;
    const uint32_t d = sb + OFF_W;
#pragma unroll
    for (int i = 0; i < 17; i++)
        cp16(d + (i * TPB + tid) * 16, s + (size_t)(i * TPB + tid) * 16);
    CP_COMMIT();
}

// 64x128 output, K=128, 3-split bf16 MMA, 32x32 warp tile (8 warps: 2x4 grid).
// Per k16 step: 8 ldsm4 -> 24 MMAs (ratio 3).
__device__ __forceinline__ void gemm_compute(char* raw, int offA, float acc[2][4][4],
                                             int w, int l) {
    const int wm = w >> 2, wn = w & 3;   // wm 0..1 (32 rows), wn 0..3 (32 cols)
    const uint32_t sb = s2u(raw);
#pragma unroll
    for (int mi = 0; mi < 2; mi++)
#pragma unroll
        for (int s = 0; s < 4; s++)
#pragma unroll
            for (int i = 0; i < 4; i++) acc[mi][s][i] = 0.f;
    const uint32_t aBase = sb + offA + (wm * 32 + (l & 15)) * XSB + (l >> 4) * 16;
    const uint32_t bBase = sb + OFF_W +
        (wn * 32 + (l & 7) + ((l >> 4) & 1) * 8) * XSB + ((l >> 3) & 1) * 16;
#pragma unroll
    for (int k8 = 0; k8 < 8; k8++) {
        uint32_t ah[2][4], al[2][4];
        ldsm4(ah[0][0], ah[0][1], ah[0][2], ah[0][3], aBase + k8 * 32);
        ldsm4(ah[1][0], ah[1][1], ah[1][2], ah[1][3], aBase + 16 * XSB + k8 * 32);
        ldsm4(al[0][0], al[0][1], al[0][2], al[0][3], aBase + XH64 + k8 * 32);
        ldsm4(al[1][0], al[1][1], al[1][2], al[1][3], aBase + XH64 + 16 * XSB + k8 * 32);
        uint32_t bh[8], bl[8];
        ldsm4(bh[0], bh[1], bh[2], bh[3], bBase + k8 * 32);              // subs 0,1
        ldsm4(bh[4], bh[5], bh[6], bh[7], bBase + 16 * XSB + k8 * 32);   // subs 2,3
        ldsm4(bl[0], bl[1], bl[2], bl[3], bBase + WHALF + k8 * 32);
        ldsm4(bl[4], bl[5], bl[6], bl[7], bBase + WHALF + 16 * XSB + k8 * 32);
#pragma unroll
        for (int mi = 0; mi < 2; mi++)
#pragma unroll
            for (int sub = 0; sub < 4; sub++) {
                mma_bf16(acc[mi][sub], ah[mi], bh[2 * sub], bh[2 * sub + 1]);  // hi*hi
                mma_bf16(acc[mi][sub], ah[mi], bl[2 * sub], bl[2 * sub + 1]);  // hi*lo
                mma_bf16(acc[mi][sub], al[mi], bh[2 * sub], bh[2 * sub + 1]);  // lo*hi
            }
    }
}
__device__ __forceinline__ void epilogue(const float acc[2][4][4], const float* bias,
                                         float scale, float* dst, int dstride,
                                         int w, int l) {
    const int wm = w >> 2, wn = w & 3;
#pragma unroll
    for (int mi = 0; mi < 2; mi++) {
        const int r0 = wm * 32 + mi * 16 + (l >> 2);
#pragma unroll
        for (int sub = 0; sub < 4; sub++) {
            const int cb = wn * 32 + sub * 8 + (l & 3) * 2;
            float2 v;
            v.x = (acc[mi][sub][0] + bias[cb]) * scale;
            v.y = (acc[mi][sub][1] + bias[cb + 1]) * scale;
            *reinterpret_cast<float2*>(dst + r0 * dstride + cb) = v;
            v.x = (acc[mi][sub][2] + bias[cb]) * scale;
            v.y = (acc[mi][sub][3] + bias[cb + 1]) * scale;
            *reinterpret_cast<float2*>(dst + (r0 + 8) * dstride + cb) = v;
        }
    }
}

// ---------- pre-kernel: weights f32 -> bf16 hi/lo tiles in g_wconv ----------
extern "C" __global__ void wconv_kernel(const float* __restrict__ wq,
                                        const float* __restrict__ wk,
                                        const float* __restrict__ wv,
                                        const float* __restrict__ wo) {
    const int idx = (blockIdx.x * blockDim.x + threadIdx.x) * 4;
    const int wsel = idx >> 14;
    const float* W = (wsel == 0) ? wq : (wsel == 1) ? wk : (wsel == 2) ? wv : wo;
    const int rem = idx & 16383;
    const int c = rem >> 7, k = rem & 127;
    float4 x = *reinterpret_cast<const float4*>(W + c * 128 + k);
    ull hw, lw; split4(x, hw, lw);
    *(ull*)(g_wconv + wsel * WB + c * XSB + k * 2)         = hw;
    *(ull*)(g_wconv + wsel * WB + WHALF + c * XSB + k * 2) = lw;
}

// ---------- main fused kernel: 2 graphs per CTA, 8 warps ----------
extern "C" __global__ void __launch_bounds__(TPB, 1)
iattn_mma4_kernel(const float* __restrict__ query, const float* __restrict__ key,
                  const float* __restrict__ value,
                  const float* __restrict__ bq, const float* __restrict__ bk,
                  const float* __restrict__ bv, const float* __restrict__ bo,
                  float* __restrict__ out)
{
    extern __shared__ char raw[];
    const int tid = threadIdx.x;
    const int w = tid >> 5, l = tid & 31;
    const size_t base = (size_t)blockIdx.x * 64 * E_DIM;
    const uint32_t sb = s2u(raw);
    float* bias_s = reinterpret_cast<float*>(raw + OFF_BIAS);

    copy_W_async(0, sb, tid);              // Wq overlaps bias + convert
    {
        const float* b0 = (tid < 128) ? bq : bk;
        bias_s[tid] = b0[tid & 127];
        const float* b1 = (tid < 128) ? bv : bo;
        bias_s[tid + 256] = b1[tid & 127];
    }

    float acc[2][4][4];
    const float* gx[3]  = {query + base, key + base, value + base};
    const int   offD[3] = {OFF_C, OFF_D, OFF_X};
    const float scl[3]  = {0.25f, 1.0f, 1.0f};

    // --- projection phases ---
#pragma unroll
    for (int ph = 0; ph < 3; ph++) {
        convert_X(gx[ph], raw, tid);
        CP_WAIT0();
        __syncthreads();                   // X + W visible
        gemm_compute(raw, OFF_X, acc, w, l);
        __syncthreads();                   // all gemm reads of X/W done
        epilogue(acc, bias_s + ph * 128, scl[ph],
                 reinterpret_cast<float*>(raw + offD[ph]), PAD, w, l);
        copy_W_async(ph + 1, sb, tid);     // next weight (Wo when ph==2)
    }
    CP_WAIT0();
    __syncthreads();                       // Q_s/K_s/V_s + Wo visible

    // --- attention: warp = head w; loops both graphs; outputs buffered ---
    {
        const float* Qs = reinterpret_cast<const float*>(raw + OFF_C);
        const float* Ks = reinterpret_cast<const float*>(raw + OFF_D);
        const float* Vs = reinterpret_cast<const float*>(raw + OFF_X);
        const int c0 = w * 16;
        float oall[2][16];
#pragma unroll
        for (int g = 0; g < 2; g++) {
            const float* qr = Qs + (g * NPG + l) * PAD + c0;
            ulonglong2 qa = *reinterpret_cast<const ulonglong2*>(qr);
            ulonglong2 qb = *reinterpret_cast<const ulonglong2*>(qr + 4);
            ulonglong2 qc = *reinterpret_cast<const ulonglong2*>(qr + 8);
            ulonglong2 qd = *reinterpret_cast<const ulonglong2*>(qr + 12);

            float sc[NPG];
            float mx = -1e30f;
#pragma unroll
            for (int j = 0; j < NPG; j++) {
                const float* kr = Ks + (g * NPG + j) * PAD + c0;
                ulonglong2 ka = *reinterpret_cast<const ulonglong2*>(kr);
                ulonglong2 kb = *reinterpret_cast<const ulonglong2*>(kr + 4);
                ulonglong2 kc = *reinterpret_cast<const ulonglong2*>(kr + 8);
                ulonglong2 kd = *reinterpret_cast<const ulonglong2*>(kr + 12);
                ull t2 = 0ULL;
                ffma2(t2, qa.x, ka.x); ffma2(t2, qa.y, ka.y);
                ffma2(t2, qb.x, kb.x); ffma2(t2, qb.y, kb.y);
                ffma2(t2, qc.x, kc.x); ffma2(t2, qc.y, kc.y);
                ffma2(t2, qd.x, kd.x); ffma2(t2, qd.y, kd.y);
                float tl, th; unpack2(t2, tl, th);
                const float t = tl + th;
                sc[j] = t;
                mx = fmaxf(mx, t);
            }
            float sum = 0.f;
#pragma unroll
            for (int j = 0; j < NPG; j++) { sc[j] = __expf(sc[j] - mx); sum += sc[j]; }
            const float inv = 1.0f / sum;

            ull o2[8];
#pragma unroll
            for (int i = 0; i < 8; i++) o2[i] = 0ULL;
#pragma unroll
            for (int j = 0; j < NPG; j++) {
                const ull p2 = pack2(sc[j], sc[j]);
                const float* vr = Vs + (g * NPG + j) * PAD + c0;
                ulonglong2 va = *reinterpret_cast<const ulonglong2*>(vr);
                ulonglong2 vb = *reinterpret_cast<const ulonglong2*>(vr + 4);
                ulonglong2 vc = *reinterpret_cast<const ulonglong2*>(vr + 8);
                ulonglong2 vd = *reinterpret_cast<const ulonglong2*>(vr + 12);
                ffma2(o2[0], p2, va.x); ffma2(o2[1], p2, va.y);
                ffma2(o2[2], p2, vb.x); ffma2(o2[3], p2, vb.y);
                ffma2(o2[4], p2, vc.x); ffma2(o2[5], p2, vc.y);
                ffma2(o2[6], p2, vd.x); ffma2(o2[7], p2, vd.y);
            }
#pragma unroll
            for (int i = 0; i < 8; i++) {
                float lo, hi; unpack2(o2[i], lo, hi);
                oall[g][2 * i]     = lo * inv;
                oall[g][2 * i + 1] = hi * inv;
            }
        }
        __syncthreads();   // all Q_s reads done before overlaying OFF_C
#pragma unroll
        for (int g = 0; g < 2; g++) {
            const int row = g * NPG + l;
#pragma unroll
            for (int p = 0; p < 4; p++) {
                float4 x = make_float4(oall[g][4 * p], oall[g][4 * p + 1],
                                       oall[g][4 * p + 2], oall[g][4 * p + 3]);
                ull hw, lw; split4(x, hw, lw);
                const int col = c0 + 4 * p;
                *(ull*)(raw + OFF_C + row * XSB + col * 2)        = hw;
                *(ull*)(raw + OFF_C + XH64 + row * XSB + col * 2) = lw;
            }
        }
    }
    __syncthreads();   // attn-out tiles complete

    // --- out projection -> gmem ---
    gemm_compute(raw, OFF_C, acc, w, l);
    epilogue(acc, bias_s + 384, 1.0f, out + base, E_DIM, w, l);
}

extern "C" void kernel_launch(void* const* d_in, const int* in_sizes, int n_in,
                              void* d_out, int out_size)
{
    const float* query = (const float*)d_in[0];
    const float* key_  = (const float*)d_in[1];
    const float* value = (const float*)d_in[2];
    const float* wq    = (const float*)d_in[3];
    const float* wk    = (const float*)d_in[4];
    const float* wv    = (const float*)d_in[5];
    const float* bq    = (const float*)d_in[6];
    const float* bk    = (const float*)d_in[7];
    const float* bv    = (const float*)d_in[8];
    const float* wo    = (const float*)d_in[9];
    const float* bo    = (const float*)d_in[10];
    float* out = (float*)d_out;

    const int N = in_sizes[0] / E_DIM;   // total nodes
    const int grid = N / 64;             // 2 graphs per CTA

    wconv_kernel<<<64, 256>>>(wq, wk, wv, wo);

    cudaFuncSetAttribute(iattn_mma4_kernel,
                         cudaFuncAttributeMaxDynamicSharedMemorySize, SMEM_TOTAL);
    iattn_mma4_kernel<<<grid, TPB, SMEM_TOTAL>>>(
        query, key_, value, bq, bk, bv, bo, out);
}